// round 12
// baseline (speedup 1.0000x reference)
#include <cuda_runtime.h>
#include <cuda_fp16.h>
#include <math.h>
#include <stdint.h>

#define MM   16384
#define DD   512
#define FF   2048
#define NITER 11
#define THRESH (1.0f - 0.01f)

// SMEM tile geometry (fp16): 128 rows x (32 data + 8 pad) halves = 80B pitch
#define AP       40
#define TILE_HB  (128 * AP * 2)          // 10240 B per matrix
#define STAGE_B  (4 * TILE_HB)           // Ah, Al, Bh, Bl = 40960 B
#define NSTAGE   2
#define DYN_SMEM (NSTAGE * STAGE_B)      // 81920 B -> 2 CTAs/SM

// Epilogue staging grid: 128 rows x 68 half2 cells (64 data + 4 pad)
#define EPI_PITCH 68
#define EPI_PART  (128 * EPI_PITCH)

#define NGEMM_CTA 296                    // 2 per SM
#define NPONDER_CTA 512

// Device scratch
__device__ float  g_st[(size_t)MM * DD];       // fp32 carried state
__device__ __half g_s_hi[(size_t)MM * DD];     // compact split s
__device__ __half g_s_lo[(size_t)MM * DD];
__device__ __half g_h_hi[(size_t)MM * FF];     // compact split hidden
__device__ __half g_h_lo[(size_t)MM * FF];
__device__ __half g_w1_hi[(size_t)FF * DD];    // W1^T [F][D]
__device__ __half g_w1_lo[(size_t)FF * DD];
__device__ __half g_w2_hi[(size_t)DD * FF];    // W2^T [D][F]
__device__ __half g_w2_lo[(size_t)DD * FF];
__device__ float  g_hp[MM];
__device__ float  g_uw[MM];
__device__ int    g_idx[MM];
__device__ int    g_nact[NITER + 1];
__device__ int    g_flag[NITER + 1];

// ---------------------------------------------------------------------------
__device__ __forceinline__ void cp_async16_s(uint32_t dst, const void* src) {
    asm volatile("cp.async.cg.shared.global [%0], [%1], 16;\n" :: "r"(dst), "l"(src));
}
template<int N> __device__ __forceinline__ void cp_wait() {
    asm volatile("cp.async.wait_group %0;\n" :: "n"(N) : "memory");
}

__device__ __forceinline__ void f16_split(float v, __half& hi, __half& lo) {
    hi = __float2half_rn(v);
    lo = __float2half_rn(v - __half2float(hi));
}

__device__ __forceinline__ void ldsm_x4(uint32_t& r0, uint32_t& r1,
                                        uint32_t& r2, uint32_t& r3, uint32_t a) {
    asm volatile("ldmatrix.sync.aligned.m8n8.x4.shared.b16 {%0,%1,%2,%3}, [%4];"
                 : "=r"(r0), "=r"(r1), "=r"(r2), "=r"(r3) : "r"(a));
}

__device__ __forceinline__ void mma_f16(float4& d,
    uint32_t a0, uint32_t a1, uint32_t a2, uint32_t a3,
    uint32_t b0, uint32_t b1) {
    asm volatile(
        "mma.sync.aligned.m16n8k16.row.col.f32.f16.f16.f32 "
        "{%0,%1,%2,%3}, {%4,%5,%6,%7}, {%8,%9}, {%0,%1,%2,%3};"
        : "+f"(d.x), "+f"(d.y), "+f"(d.z), "+f"(d.w)
        : "r"(a0), "r"(a1), "r"(a2), "r"(a3), "r"(b0), "r"(b1));
}

// ---------------------------------------------------------------------------
__global__ void init_kernel(const float* __restrict__ state, float* __restrict__ out)
{
    size_t i = (size_t)blockIdx.x * blockDim.x + threadIdx.x;
    if (i < (size_t)MM * DD) {
        g_st[i] = state[i];
        out[i]  = 0.0f;
    }
    if (i < MM) {
        g_hp[i] = 0.0f;
        out[(size_t)MM * DD + i] = 0.0f;
        out[(size_t)MM * DD + MM + i] = 0.0f;
    }
    if (i <= NITER) { g_flag[i] = (i == 0) ? 1 : 0; g_nact[i] = 0; }
}

// Coalesced transpose + split: W[K][N] -> Th/Tl [N][K] via 32x32 smem tile
__global__ void wsplit_kernel(const float* __restrict__ W,
                              __half* __restrict__ Th, __half* __restrict__ Tl,
                              int K, int N)
{
    __shared__ float tile[32][33];
    const int bx = blockIdx.x;        // N / 32
    const int by = blockIdx.y;        // K / 32
    const int x = threadIdx.x;        // 0..31
    const int y = threadIdx.y;        // 0..7
    #pragma unroll
    for (int j = 0; j < 4; ++j)
        tile[y + j * 8][x] = W[(size_t)(by * 32 + y + j * 8) * N + bx * 32 + x];
    __syncthreads();
    #pragma unroll
    for (int j = 0; j < 4; ++j) {
        float v = tile[x][y + j * 8];
        __half hi, lo;
        f16_split(v, hi, lo);
        size_t o = (size_t)(bx * 32 + y + j * 8) * K + by * 32 + x;
        Th[o] = hi;
        Tl[o] = lo;
    }
}

// ---------------------------------------------------------------------------
// Fused ponder + prep (bit-identical halting math), 512-block grid-stride
// ---------------------------------------------------------------------------
__global__ void ponder_kernel(const float* __restrict__ step_emb,
                              const float* __restrict__ Wp,
                              const float* __restrict__ bp,
                              float* __restrict__ out_nup,
                              float* __restrict__ out_rem,
                              int t)
{
    if (!g_flag[t]) return;
    const int warp = threadIdx.x >> 5;
    const int lane = threadIdx.x & 31;

    __shared__ int s_active;
    if (threadIdx.x == 0) s_active = 0;
    __syncthreads();

    for (int row = blockIdx.x * 8 + warp; row < MM; row += NPONDER_CTA * 8) {
        float hp = g_hp[row];
        if (hp >= 1.0f) continue;

        const float4* st4 = (const float4*)(g_st + (size_t)row * DD);
        const float4* e4  = (const float4*)(step_emb + (size_t)t * DD);
        const float4* w4  = (const float4*)Wp;

        float4 sv[4];
        float dot = 0.0f;
        #pragma unroll
        for (int j = 0; j < 4; ++j) {
            int i = lane + j * 32;
            float4 s = st4[i], e = e4[i], w = w4[i];
            sv[j].x = s.x + e.x; sv[j].y = s.y + e.y;
            sv[j].z = s.z + e.z; sv[j].w = s.w + e.w;
            dot += sv[j].x * w.x + sv[j].y * w.y
                 + sv[j].z * w.z + sv[j].w * w.w;
        }
        #pragma unroll
        for (int o = 16; o; o >>= 1) dot += __shfl_xor_sync(0xffffffffu, dot, o);

        int pos = 0;
        if (lane == 0) {
            float p = 1.0f / (1.0f + expf(-(dot + bp[0])));
            float q  = hp + p;
            float nh = (q >  THRESH) ? 1.0f : 0.0f;
            float st = (q <= THRESH) ? 1.0f : 0.0f;
            hp = hp + p * st;
            float rem = out_rem[row] + nh * (1.0f - hp);
            hp = hp + nh * rem;
            out_nup[row] += 1.0f;
            g_hp[row]    = hp;
            out_rem[row] = rem;
            g_uw[row]    = p * st + nh * rem;
            pos = atomicAdd(&g_nact[t], 1);
            g_idx[pos] = row;
            if (hp < 1.0f) atomicOr(&s_active, 1);
        }
        pos = __shfl_sync(0xffffffffu, pos, 0);

        __half2* ph = (__half2*)(g_s_hi + (size_t)pos * DD);
        __half2* pl = (__half2*)(g_s_lo + (size_t)pos * DD);
        #pragma unroll
        for (int j = 0; j < 4; ++j) {
            int c2 = (lane + j * 32) * 2;
            __half h0, l0, h1, l1, h2, l2, h3, l3;
            f16_split(sv[j].x, h0, l0);
            f16_split(sv[j].y, h1, l1);
            f16_split(sv[j].z, h2, l2);
            f16_split(sv[j].w, h3, l3);
            ph[c2]     = __halves2half2(h0, h1);
            ph[c2 + 1] = __halves2half2(h2, h3);
            pl[c2]     = __halves2half2(l0, l1);
            pl[c2 + 1] = __halves2half2(l2, l3);
        }
    }
    __syncthreads();
    if (threadIdx.x == 0 && s_active) atomicOr(&g_flag[t + 1], 1);
}

// ---------------------------------------------------------------------------
// HMMA fp16-split GEMM: grid-stride over 128x128 tiles, fixed 296-CTA grid.
// Mainloop identical to the proven R6/R11 core (8 warps x 64x32, BK=32,
// 2-stage cp.async, 2 CTAs/SM).
// MODE 0: g_h = relu(g_s @ W1' + b1), smem-staged coalesced epilogue
// MODE 1: h = g_h @ W2' + b2 (masked); out_prev[row]+=h*uw; g_st[row]=h
// ---------------------------------------------------------------------------
template<int KDIM, int NDIM, int MODE>
__global__ __launch_bounds__(256, 2) void gemm_hmma(
    const float* __restrict__ bias,
    const float* __restrict__ mask,
    float* __restrict__ out_prev, int t)
{
    const int nact = g_nact[t];
    const int MB = (nact + 127) >> 7;
    constexpr int NB = NDIM / 128;
    const int TILES = MB * NB;

    extern __shared__ unsigned char smem_raw[];
    uint32_t sb;
    asm("{ .reg .u64 tt; cvta.to.shared.u64 tt, %1; cvt.u32.u64 %0, tt; }"
        : "=r"(sb) : "l"(smem_raw));

    const int tid  = threadIdx.x;
    const int tl   = tid >> 6;
    const int u    = tid & 63;
    const uint32_t tile_off = (uint32_t)tl * TILE_HB;
    const int lane = tid & 31;
    const int w    = tid >> 5;
    const int wm   = (w >> 2) * 64;
    const int wn   = (w & 3) * 32;
    const int lr   = lane & 15;
    const int lc   = (lane >> 4) * 8;
    const int g    = lane >> 2;
    const int q    = lane & 3;

    for (int tk = blockIdx.x; tk < TILES; tk += NGEMM_CTA) {
        const int bm = (tk / NB) * 128;
        const int bn = (tk % NB) * 128;

        const __half* Ahg = ((MODE == 0) ? g_s_hi : g_h_hi) + (size_t)bm * KDIM;
        const __half* Alg = ((MODE == 0) ? g_s_lo : g_h_lo) + (size_t)bm * KDIM;
        const __half* Bhg = ((MODE == 0) ? g_w1_hi : g_w2_hi) + (size_t)bn * KDIM;
        const __half* Blg = ((MODE == 0) ? g_w1_lo : g_w2_lo) + (size_t)bn * KDIM;
        const __half* tp = (tl == 0) ? Ahg : (tl == 1) ? Alg
                         : (tl == 2) ? Bhg : Blg;

        #define LOAD_STAGE(slot, k0)                                           \
            do {                                                               \
                uint32_t dst_ = sb + (uint32_t)(slot) * STAGE_B + tile_off;    \
                _Pragma("unroll")                                              \
                for (int j_ = 0; j_ < 8; ++j_) {                               \
                    int ch_ = u + j_ * 64;                                     \
                    int row_ = ch_ >> 2, c_ = ch_ & 3;                         \
                    cp_async16_s(dst_ + (uint32_t)(row_ * (AP * 2) + c_ * 16), \
                                 tp + (size_t)row_ * KDIM + (k0) + c_ * 8);    \
                }                                                              \
                asm volatile("cp.async.commit_group;" ::: "memory");           \
            } while (0)

        constexpr int KT = KDIM / 32;
        LOAD_STAGE(0, 0);
        cp_wait<0>();
        __syncthreads();

        float4 acc[4][4];
        #pragma unroll
        for (int i = 0; i < 4; ++i)
            #pragma unroll
            for (int j = 0; j < 4; ++j)
                acc[i][j] = make_float4(0.f, 0.f, 0.f, 0.f);

        #pragma unroll 1
        for (int kt = 0; kt < KT; ++kt) {
            if (kt + 1 < KT) LOAD_STAGE((kt + 1) & 1, (kt + 1) * 32);
            const uint32_t stg = sb + (uint32_t)(kt & 1) * STAGE_B;

            #pragma unroll
            for (int sub = 0; sub < 2; ++sub) {
                const int k0 = sub * 16;
                uint32_t bh[4][2], bl[4][2];
                #pragma unroll
                for (int njp = 0; njp < 2; ++njp) {
                    uint32_t addr = stg + 2 * TILE_HB
                        + (uint32_t)(((wn + njp * 16 + lr) * AP + k0 + lc) * 2);
                    uint32_t r0, r1, r2, r3;
                    ldsm_x4(r0, r1, r2, r3, addr);
                    bh[njp * 2][0] = r0; bh[njp * 2][1] = r2;
                    bh[njp * 2 + 1][0] = r1; bh[njp * 2 + 1][1] = r3;
                    addr += TILE_HB;
                    ldsm_x4(r0, r1, r2, r3, addr);
                    bl[njp * 2][0] = r0; bl[njp * 2][1] = r2;
                    bl[njp * 2 + 1][0] = r1; bl[njp * 2 + 1][1] = r3;
                }
                #pragma unroll
                for (int mi = 0; mi < 4; ++mi) {
                    uint32_t addr = stg
                        + (uint32_t)(((wm + mi * 16 + lr) * AP + k0 + lc) * 2);
                    uint32_t ah0, ah1, ah2, ah3, al0, al1, al2, al3;
                    ldsm_x4(ah0, ah1, ah2, ah3, addr);
                    ldsm_x4(al0, al1, al2, al3, addr + TILE_HB);
                    #pragma unroll
                    for (int nj = 0; nj < 4; ++nj) {
                        mma_f16(acc[mi][nj], ah0, ah1, ah2, ah3, bh[nj][0], bh[nj][1]);
                        mma_f16(acc[mi][nj], ah0, ah1, ah2, ah3, bl[nj][0], bl[nj][1]);
                        mma_f16(acc[mi][nj], al0, al1, al2, al3, bh[nj][0], bh[nj][1]);
                    }
                }
            }

            if (kt + 1 < KT) {
                cp_wait<0>();
                __syncthreads();
            }
        }
        #undef LOAD_STAGE

        if (MODE == 0) {
            // staged epilogue: acc -> smem -> coalesced 16B stores
            __syncthreads();
            __half2* stage = (__half2*)smem_raw;
            #pragma unroll
            for (int mi = 0; mi < 4; ++mi) {
                #pragma unroll
                for (int half = 0; half < 2; ++half) {
                    const int mloc = wm + mi * 16 + g + half * 8;
                    #pragma unroll
                    for (int nj = 0; nj < 4; ++nj) {
                        const int col = wn + nj * 8 + 2 * q;
                        float v0 = half ? acc[mi][nj].z : acc[mi][nj].x;
                        float v1 = half ? acc[mi][nj].w : acc[mi][nj].y;
                        v0 = fmaxf(v0 + bias[bn + col], 0.0f);
                        v1 = fmaxf(v1 + bias[bn + col + 1], 0.0f);
                        __half h0, l0, h1, l1;
                        f16_split(v0, h0, l0);
                        f16_split(v1, h1, l1);
                        const int cell = mloc * EPI_PITCH + (col >> 1);
                        stage[cell]            = __halves2half2(h0, h1);
                        stage[EPI_PART + cell] = __halves2half2(l0, l1);
                    }
                }
            }
            __syncthreads();
            #pragma unroll
            for (int it = 0; it < 8; ++it) {
                int idx = tid + it * 256;
                int rw = idx >> 4, cu = idx & 15;
                int m = bm + rw;
                if (m >= nact) continue;
                const uint4* shi = (const uint4*)(stage + rw * EPI_PITCH);
                const uint4* slo = (const uint4*)(stage + EPI_PART + rw * EPI_PITCH);
                *(uint4*)(g_h_hi + (size_t)m * NDIM + bn + cu * 8) = shi[cu];
                *(uint4*)(g_h_lo + (size_t)m * NDIM + bn + cu * 8) = slo[cu];
            }
            __syncthreads();   // protect stage smem before next tile's loads
        } else {
            #pragma unroll
            for (int mi = 0; mi < 4; ++mi) {
                #pragma unroll
                for (int half = 0; half < 2; ++half) {
                    const int m = bm + wm + mi * 16 + g + half * 8;
                    if (m >= nact) continue;
                    const int row = g_idx[m];
                    const float mk  = mask[row];
                    const float uwv = g_uw[row];
                    #pragma unroll
                    for (int nj = 0; nj < 4; ++nj) {
                        const int col = bn + wn + nj * 8 + 2 * q;
                        float v0 = half ? acc[mi][nj].z : acc[mi][nj].x;
                        float v1 = half ? acc[mi][nj].w : acc[mi][nj].y;
                        float h0 = (v0 + bias[col])     * mk;
                        float h1 = (v1 + bias[col + 1]) * mk;
                        float* pp = out_prev + (size_t)row * NDIM + col;
                        float* sp = g_st     + (size_t)row * NDIM + col;
                        float2 pv = *(const float2*)pp;
                        pv.x += h0 * uwv;
                        pv.y += h1 * uwv;
                        *(float2*)pp = pv;
                        *(float2*)sp = make_float2(h0, h1);
                    }
                }
            }
        }
    }
}

// ---------------------------------------------------------------------------
extern "C" void kernel_launch(void* const* d_in, const int* in_sizes, int n_in,
                              void* d_out, int out_size)
{
    const float* state    = (const float*)d_in[0];
    const float* mask     = (const float*)d_in[1];
    const float* step_emb = (const float*)d_in[2];
    const float* Wp       = (const float*)d_in[3];
    const float* bp       = (const float*)d_in[4];
    const float* W1       = (const float*)d_in[5];
    const float* b1       = (const float*)d_in[6];
    const float* W2       = (const float*)d_in[7];
    const float* b2       = (const float*)d_in[8];

    float* out     = (float*)d_out;
    float* out_nup = out + (size_t)MM * DD;
    float* out_rem = out_nup + MM;

    cudaFuncSetAttribute(gemm_hmma<DD, FF, 0>,
        cudaFuncAttributeMaxDynamicSharedMemorySize, DYN_SMEM);
    cudaFuncSetAttribute(gemm_hmma<FF, DD, 1>,
        cudaFuncAttributeMaxDynamicSharedMemorySize, DYN_SMEM);

    init_kernel<<<(MM * DD + 255) / 256, 256>>>(state, out);

    {
        __half *w1h, *w1l, *w2h, *w2l;
        cudaGetSymbolAddress((void**)&w1h, g_w1_hi);
        cudaGetSymbolAddress((void**)&w1l, g_w1_lo);
        cudaGetSymbolAddress((void**)&w2h, g_w2_hi);
        cudaGetSymbolAddress((void**)&w2l, g_w2_lo);
        dim3 tb(32, 8);
        wsplit_kernel<<<dim3(FF / 32, DD / 32), tb>>>(W1, w1h, w1l, DD, FF);
        wsplit_kernel<<<dim3(DD / 32, FF / 32), tb>>>(W2, w2h, w2l, FF, DD);
    }

    for (int t = 0; t < NITER; ++t) {
        ponder_kernel<<<NPONDER_CTA, 256>>>(step_emb, Wp, bp, out_nup, out_rem, t);
        gemm_hmma<DD, FF, 0><<<NGEMM_CTA, 256, DYN_SMEM>>>(b1, nullptr, nullptr, t);
        gemm_hmma<FF, DD, 1><<<NGEMM_CTA, 256, DYN_SMEM>>>(b2, mask, out, t);
    }
}

// round 13
// speedup vs baseline: 1.0284x; 1.0284x over previous
#include <cuda_runtime.h>
#include <cuda_fp16.h>
#include <math.h>
#include <stdint.h>

#define MM   16384
#define DD   512
#define FF   2048
#define NITER 11
#define THRESH (1.0f - 0.01f)

// SMEM tile geometry (fp16): 128 rows x (32 data + 8 pad) halves = 80B pitch
#define AP       40
#define TILE_HB  (128 * AP * 2)          // 10240 B per matrix
#define STAGE_B  (4 * TILE_HB)           // Ah, Al, Bh, Bl = 40960 B
#define NSTAGE   2
#define DYN_SMEM (NSTAGE * STAGE_B)      // 81920 B -> 2 CTAs/SM

// Epilogue staging grid: 128 rows x 68 half2 cells (64 data + 4 pad)
#define EPI_PITCH 68
#define EPI_PART  (128 * EPI_PITCH)

// Device scratch
__device__ float  g_st[(size_t)MM * DD];       // fp32 carried state
__device__ __half g_s_hi[(size_t)MM * DD];     // compact split s
__device__ __half g_s_lo[(size_t)MM * DD];
__device__ __half g_h_hi[(size_t)MM * FF];     // compact split hidden
__device__ __half g_h_lo[(size_t)MM * FF];
__device__ __half g_w1_hi[(size_t)FF * DD];    // W1^T [F][D]
__device__ __half g_w1_lo[(size_t)FF * DD];
__device__ __half g_w2_hi[(size_t)DD * FF];    // W2^T [D][F]
__device__ __half g_w2_lo[(size_t)DD * FF];
__device__ float  g_hp[MM];
__device__ float  g_uw[MM];
__device__ int    g_idx[MM];
__device__ int    g_nact[NITER + 1];
__device__ int    g_flag[NITER + 1];

// ---------------------------------------------------------------------------
__device__ __forceinline__ void cp_async16_s(uint32_t dst, const void* src) {
    asm volatile("cp.async.cg.shared.global [%0], [%1], 16;\n" :: "r"(dst), "l"(src));
}
template<int N> __device__ __forceinline__ void cp_wait() {
    asm volatile("cp.async.wait_group %0;\n" :: "n"(N) : "memory");
}

__device__ __forceinline__ void f16_split(float v, __half& hi, __half& lo) {
    hi = __float2half_rn(v);
    lo = __float2half_rn(v - __half2float(hi));
}

__device__ __forceinline__ void ldsm_x4(uint32_t& r0, uint32_t& r1,
                                        uint32_t& r2, uint32_t& r3, uint32_t a) {
    asm volatile("ldmatrix.sync.aligned.m8n8.x4.shared.b16 {%0,%1,%2,%3}, [%4];"
                 : "=r"(r0), "=r"(r1), "=r"(r2), "=r"(r3) : "r"(a));
}

__device__ __forceinline__ void mma_f16(float4& d,
    uint32_t a0, uint32_t a1, uint32_t a2, uint32_t a3,
    uint32_t b0, uint32_t b1) {
    asm volatile(
        "mma.sync.aligned.m16n8k16.row.col.f32.f16.f16.f32 "
        "{%0,%1,%2,%3}, {%4,%5,%6,%7}, {%8,%9}, {%0,%1,%2,%3};"
        : "+f"(d.x), "+f"(d.y), "+f"(d.z), "+f"(d.w)
        : "r"(a0), "r"(a1), "r"(a2), "r"(a3), "r"(b0), "r"(b1));
}

// ---------------------------------------------------------------------------
__global__ void init_kernel(const float* __restrict__ state, float* __restrict__ out)
{
    size_t i = (size_t)blockIdx.x * blockDim.x + threadIdx.x;
    if (i < (size_t)MM * DD) {
        g_st[i] = state[i];
        out[i]  = 0.0f;
    }
    if (i < MM) {
        g_hp[i] = 0.0f;
        out[(size_t)MM * DD + i] = 0.0f;
        out[(size_t)MM * DD + MM + i] = 0.0f;
    }
    if (i <= NITER) { g_flag[i] = (i == 0) ? 1 : 0; g_nact[i] = 0; }
}

// Coalesced transpose + split: W[K][N] -> Th/Tl [N][K] via 32x32 smem tile
__global__ void wsplit_kernel(const float* __restrict__ W,
                              __half* __restrict__ Th, __half* __restrict__ Tl,
                              int K, int N)
{
    __shared__ float tile[32][33];
    const int bx = blockIdx.x;        // N / 32
    const int by = blockIdx.y;        // K / 32
    const int x = threadIdx.x;        // 0..31
    const int y = threadIdx.y;        // 0..7
    #pragma unroll
    for (int j = 0; j < 4; ++j)
        tile[y + j * 8][x] = W[(size_t)(by * 32 + y + j * 8) * N + bx * 32 + x];
    __syncthreads();
    #pragma unroll
    for (int j = 0; j < 4; ++j) {
        float v = tile[x][y + j * 8];
        __half hi, lo;
        f16_split(v, hi, lo);
        size_t o = (size_t)(bx * 32 + y + j * 8) * K + by * 32 + x;
        Th[o] = hi;
        Tl[o] = lo;
    }
}

// ---------------------------------------------------------------------------
// Fused ponder + prep (bit-identical halting math; R11 grid: warp per row)
// ---------------------------------------------------------------------------
__global__ void ponder_kernel(const float* __restrict__ step_emb,
                              const float* __restrict__ Wp,
                              const float* __restrict__ bp,
                              float* __restrict__ out_nup,
                              float* __restrict__ out_rem,
                              int t)
{
    if (!g_flag[t]) return;
    int row  = blockIdx.x * 8 + (threadIdx.x >> 5);
    int lane = threadIdx.x & 31;

    __shared__ int s_active;
    if (threadIdx.x == 0) s_active = 0;
    __syncthreads();

    float hp = g_hp[row];
    if (hp < 1.0f) {
        const float4* st4 = (const float4*)(g_st + (size_t)row * DD);
        const float4* e4  = (const float4*)(step_emb + (size_t)t * DD);
        const float4* w4  = (const float4*)Wp;

        float4 sv[4];
        float dot = 0.0f;
        #pragma unroll
        for (int j = 0; j < 4; ++j) {
            int i = lane + j * 32;
            float4 s = st4[i], e = e4[i], w = w4[i];
            sv[j].x = s.x + e.x; sv[j].y = s.y + e.y;
            sv[j].z = s.z + e.z; sv[j].w = s.w + e.w;
            dot += sv[j].x * w.x + sv[j].y * w.y
                 + sv[j].z * w.z + sv[j].w * w.w;
        }
        #pragma unroll
        for (int o = 16; o; o >>= 1) dot += __shfl_xor_sync(0xffffffffu, dot, o);

        int pos = 0;
        if (lane == 0) {
            float p = 1.0f / (1.0f + expf(-(dot + bp[0])));
            float q  = hp + p;
            float nh = (q >  THRESH) ? 1.0f : 0.0f;
            float st = (q <= THRESH) ? 1.0f : 0.0f;
            hp = hp + p * st;
            float rem = out_rem[row] + nh * (1.0f - hp);
            hp = hp + nh * rem;
            out_nup[row] += 1.0f;
            g_hp[row]    = hp;
            out_rem[row] = rem;
            g_uw[row]    = p * st + nh * rem;
            pos = atomicAdd(&g_nact[t], 1);
            g_idx[pos] = row;
            if (hp < 1.0f) atomicOr(&s_active, 1);
        }
        pos = __shfl_sync(0xffffffffu, pos, 0);

        __half2* ph = (__half2*)(g_s_hi + (size_t)pos * DD);
        __half2* pl = (__half2*)(g_s_lo + (size_t)pos * DD);
        #pragma unroll
        for (int j = 0; j < 4; ++j) {
            int c2 = (lane + j * 32) * 2;
            __half h0, l0, h1, l1, h2, l2, h3, l3;
            f16_split(sv[j].x, h0, l0);
            f16_split(sv[j].y, h1, l1);
            f16_split(sv[j].z, h2, l2);
            f16_split(sv[j].w, h3, l3);
            ph[c2]     = __halves2half2(h0, h1);
            ph[c2 + 1] = __halves2half2(h2, h3);
            pl[c2]     = __halves2half2(l0, l1);
            pl[c2 + 1] = __halves2half2(l2, l3);
        }
    }
    __syncthreads();
    if (threadIdx.x == 0 && s_active) atomicOr(&g_flag[t + 1], 1);
}

// ---------------------------------------------------------------------------
// HMMA fp16-split GEMM: 128x128 CTA, 8 warps x 64x32 warp tiles, BK=32,
// 2-stage cp.async, 2 CTAs/SM. (R11 champion configuration, per-tile grid.)
// MODE 0: g_h = relu(g_s @ W1' + b1); smem-staged coalesced epilogue
// MODE 1: h = g_h @ W2' + b2 (masked); out_prev[row]+=h*uw; g_st[row]=h
// ---------------------------------------------------------------------------
template<int KDIM, int NDIM, int MODE>
__global__ __launch_bounds__(256, 2) void gemm_hmma(
    const float* __restrict__ bias,
    const float* __restrict__ mask,
    float* __restrict__ out_prev, int t)
{
    const int nact = g_nact[t];
    const int bm = blockIdx.y * 128;
    if (bm >= nact) return;
    const int bn = blockIdx.x * 128;

    extern __shared__ unsigned char smem_raw[];
    uint32_t sb;
    asm("{ .reg .u64 tt; cvta.to.shared.u64 tt, %1; cvt.u32.u64 %0, tt; }"
        : "=r"(sb) : "l"(smem_raw));

    const int tid = threadIdx.x;

    // ---- loader: 4 groups of 64 threads (Ah, Al, Bh, Bl), 8 chunks each ----
    const __half* Ahg = ((MODE == 0) ? g_s_hi : g_h_hi) + (size_t)bm * KDIM;
    const __half* Alg = ((MODE == 0) ? g_s_lo : g_h_lo) + (size_t)bm * KDIM;
    const __half* Bhg = ((MODE == 0) ? g_w1_hi : g_w2_hi) + (size_t)bn * KDIM;
    const __half* Blg = ((MODE == 0) ? g_w1_lo : g_w2_lo) + (size_t)bn * KDIM;
    const int tl = tid >> 6;
    const __half* tp = (tl == 0) ? Ahg : (tl == 1) ? Alg : (tl == 2) ? Bhg : Blg;
    const int u = tid & 63;
    const uint32_t tile_off = (uint32_t)tl * TILE_HB;

    #define LOAD_STAGE(slot, k0)                                               \
        do {                                                                   \
            uint32_t dst_ = sb + (uint32_t)(slot) * STAGE_B + tile_off;        \
            _Pragma("unroll")                                                  \
            for (int j_ = 0; j_ < 8; ++j_) {                                   \
                int ch_ = u + j_ * 64;                                         \
                int row_ = ch_ >> 2, c_ = ch_ & 3;                             \
                cp_async16_s(dst_ + (uint32_t)(row_ * (AP * 2) + c_ * 16),     \
                             tp + (size_t)row_ * KDIM + (k0) + c_ * 8);        \
            }                                                                  \
            asm volatile("cp.async.commit_group;" ::: "memory");               \
        } while (0)

    constexpr int KT = KDIM / 32;
    LOAD_STAGE(0, 0);
    cp_wait<0>();
    __syncthreads();

    // ---- warp tiling: 8 warps, 64x32 each (2x4 warp grid) ----
    const int lane = tid & 31;
    const int w    = tid >> 5;
    const int wm   = (w >> 2) * 64;
    const int wn   = (w & 3) * 32;
    const int lr   = lane & 15;
    const int lc   = (lane >> 4) * 8;

    float4 acc[4][4];
    #pragma unroll
    for (int i = 0; i < 4; ++i)
        #pragma unroll
        for (int j = 0; j < 4; ++j)
            acc[i][j] = make_float4(0.f, 0.f, 0.f, 0.f);

    #pragma unroll 1
    for (int kt = 0; kt < KT; ++kt) {
        if (kt + 1 < KT) LOAD_STAGE((kt + 1) & 1, (kt + 1) * 32);
        const uint32_t stg = sb + (uint32_t)(kt & 1) * STAGE_B;

        #pragma unroll
        for (int sub = 0; sub < 2; ++sub) {
            const int k0 = sub * 16;
            uint32_t bh[4][2], bl[4][2];
            #pragma unroll
            for (int njp = 0; njp < 2; ++njp) {
                uint32_t addr = stg + 2 * TILE_HB
                    + (uint32_t)(((wn + njp * 16 + lr) * AP + k0 + lc) * 2);
                uint32_t r0, r1, r2, r3;
                ldsm_x4(r0, r1, r2, r3, addr);
                bh[njp * 2][0] = r0; bh[njp * 2][1] = r2;
                bh[njp * 2 + 1][0] = r1; bh[njp * 2 + 1][1] = r3;
                addr += TILE_HB;
                ldsm_x4(r0, r1, r2, r3, addr);
                bl[njp * 2][0] = r0; bl[njp * 2][1] = r2;
                bl[njp * 2 + 1][0] = r1; bl[njp * 2 + 1][1] = r3;
            }
            #pragma unroll
            for (int mi = 0; mi < 4; ++mi) {
                uint32_t addr = stg
                    + (uint32_t)(((wm + mi * 16 + lr) * AP + k0 + lc) * 2);
                uint32_t ah0, ah1, ah2, ah3, al0, al1, al2, al3;
                ldsm_x4(ah0, ah1, ah2, ah3, addr);
                ldsm_x4(al0, al1, al2, al3, addr + TILE_HB);
                #pragma unroll
                for (int nj = 0; nj < 4; ++nj) {
                    mma_f16(acc[mi][nj], ah0, ah1, ah2, ah3, bh[nj][0], bh[nj][1]);
                    mma_f16(acc[mi][nj], ah0, ah1, ah2, ah3, bl[nj][0], bl[nj][1]);
                    mma_f16(acc[mi][nj], al0, al1, al2, al3, bh[nj][0], bh[nj][1]);
                }
            }
        }

        if (kt + 1 < KT) {
            cp_wait<0>();
            __syncthreads();
        }
    }
    #undef LOAD_STAGE

    const int g = lane >> 2;
    const int q = lane & 3;

    if (MODE == 0) {
        // ---- staged epilogue: acc -> smem (hi part0, lo part1) -> coalesced ----
        __syncthreads();                      // all warps done reading stages
        __half2* stage = (__half2*)smem_raw;  // [2][128][EPI_PITCH]
        #pragma unroll
        for (int mi = 0; mi < 4; ++mi) {
            #pragma unroll
            for (int half = 0; half < 2; ++half) {
                const int mloc = wm + mi * 16 + g + half * 8;
                #pragma unroll
                for (int nj = 0; nj < 4; ++nj) {
                    const int col = wn + nj * 8 + 2 * q;       // 0..126 even
                    float v0 = half ? acc[mi][nj].z : acc[mi][nj].x;
                    float v1 = half ? acc[mi][nj].w : acc[mi][nj].y;
                    v0 = fmaxf(v0 + bias[bn + col], 0.0f);
                    v1 = fmaxf(v1 + bias[bn + col + 1], 0.0f);
                    __half h0, l0, h1, l1;
                    f16_split(v0, h0, l0);
                    f16_split(v1, h1, l1);
                    const int cell = mloc * EPI_PITCH + (col >> 1);
                    stage[cell]            = __halves2half2(h0, h1);
                    stage[EPI_PART + cell] = __halves2half2(l0, l1);
                }
            }
        }
        __syncthreads();
        // coalesced output: each row = 64 half2 = 16 uint4; 128 rows x 16 = 2048
        #pragma unroll
        for (int it = 0; it < 8; ++it) {
            int idx = tid + it * 256;
            int rw = idx >> 4, cu = idx & 15;
            int m = bm + rw;
            if (m >= nact) continue;
            const uint4* shi = (const uint4*)(stage + rw * EPI_PITCH);
            const uint4* slo = (const uint4*)(stage + EPI_PART + rw * EPI_PITCH);
            *(uint4*)(g_h_hi + (size_t)m * NDIM + bn + cu * 8) = shi[cu];
            *(uint4*)(g_h_lo + (size_t)m * NDIM + bn + cu * 8) = slo[cu];
        }
    } else {
        #pragma unroll
        for (int mi = 0; mi < 4; ++mi) {
            #pragma unroll
            for (int half = 0; half < 2; ++half) {
                const int m = bm + wm + mi * 16 + g + half * 8;
                if (m >= nact) continue;
                const int row = g_idx[m];
                const float mk  = mask[row];
                const float uwv = g_uw[row];
                #pragma unroll
                for (int nj = 0; nj < 4; ++nj) {
                    const int col = bn + wn + nj * 8 + 2 * q;
                    float v0 = half ? acc[mi][nj].z : acc[mi][nj].x;
                    float v1 = half ? acc[mi][nj].w : acc[mi][nj].y;
                    float h0 = (v0 + bias[col])     * mk;
                    float h1 = (v1 + bias[col + 1]) * mk;
                    float* pp = out_prev + (size_t)row * NDIM + col;
                    float* sp = g_st     + (size_t)row * NDIM + col;
                    float2 pv = *(const float2*)pp;
                    pv.x += h0 * uwv;
                    pv.y += h1 * uwv;
                    *(float2*)pp = pv;
                    *(float2*)sp = make_float2(h0, h1);
                }
            }
        }
    }
}

// ---------------------------------------------------------------------------
extern "C" void kernel_launch(void* const* d_in, const int* in_sizes, int n_in,
                              void* d_out, int out_size)
{
    const float* state    = (const float*)d_in[0];
    const float* mask     = (const float*)d_in[1];
    const float* step_emb = (const float*)d_in[2];
    const float* Wp       = (const float*)d_in[3];
    const float* bp       = (const float*)d_in[4];
    const float* W1       = (const float*)d_in[5];
    const float* b1       = (const float*)d_in[6];
    const float* W2       = (const float*)d_in[7];
    const float* b2       = (const float*)d_in[8];

    float* out     = (float*)d_out;
    float* out_nup = out + (size_t)MM * DD;
    float* out_rem = out_nup + MM;

    cudaFuncSetAttribute(gemm_hmma<DD, FF, 0>,
        cudaFuncAttributeMaxDynamicSharedMemorySize, DYN_SMEM);
    cudaFuncSetAttribute(gemm_hmma<FF, DD, 1>,
        cudaFuncAttributeMaxDynamicSharedMemorySize, DYN_SMEM);

    init_kernel<<<(MM * DD + 255) / 256, 256>>>(state, out);

    {
        __half *w1h, *w1l, *w2h, *w2l;
        cudaGetSymbolAddress((void**)&w1h, g_w1_hi);
        cudaGetSymbolAddress((void**)&w1l, g_w1_lo);
        cudaGetSymbolAddress((void**)&w2h, g_w2_hi);
        cudaGetSymbolAddress((void**)&w2l, g_w2_lo);
        dim3 tb(32, 8);
        wsplit_kernel<<<dim3(FF / 32, DD / 32), tb>>>(W1, w1h, w1l, DD, FF);
        wsplit_kernel<<<dim3(DD / 32, FF / 32), tb>>>(W2, w2h, w2l, FF, DD);
    }

    dim3 g1(FF / 128, MM / 128);   // (16, 128)
    dim3 g2(DD / 128, MM / 128);   // (4, 128)

    for (int t = 0; t < NITER; ++t) {
        ponder_kernel<<<MM / 8, 256>>>(step_emb, Wp, bp, out_nup, out_rem, t);
        gemm_hmma<DD, FF, 0><<<g1, 256, DYN_SMEM>>>(b1, nullptr, nullptr, t);
        gemm_hmma<FF, DD, 1><<<g2, 256, DYN_SMEM>>>(b2, mask, out, t);
    }
}